// round 1
// baseline (speedup 1.0000x reference)
#include <cuda_runtime.h>
#include <cstdint>

// Problem constants
#define NB 16      // batches
#define CH 256     // c*h rows
#define SD 3200    // w*u*v contraction dim (re-ordered as s' = n*128 + w)
#define ELEM_PER_B 819200   // 16*25*16*128 floats per (batch) per tensor

// Scratch (static device globals: allowed; no runtime allocation)
__device__ float g_Qp[NB * CH * SD];
__device__ float g_Kp[NB * CH * SD];
__device__ float g_Vp[NB * CH * SD];
__device__ float g_att[NB * CH * CH];
__device__ float g_invq[NB * CH];
__device__ float g_invk[NB * CH];

// ---------------------------------------------------------------------------
// Pack: input (b, c, n, h, w) -> packed [b*256 + t][s'] with t = c*16+h,
// s' = n*128 + w. Both read and write fully coalesced (float4).
// blockIdx.y selects tensor {0:q, 1:k, 2:v}.
// ---------------------------------------------------------------------------
__global__ void pack_kernel(const float4* __restrict__ q,
                            const float4* __restrict__ k,
                            const float4* __restrict__ v) {
    int i = blockIdx.x * blockDim.x + threadIdx.x;   // [0, 3276800)
    const float4* src;
    float4* dst;
    if (blockIdx.y == 0)      { src = q; dst = (float4*)g_Qp; }
    else if (blockIdx.y == 1) { src = k; dst = (float4*)g_Kp; }
    else                      { src = v; dst = (float4*)g_Vp; }

    int w4 = i & 31;          // float4 index within w (w = w4*4..)
    int j  = i >> 5;          // (b*256+t)*25 + n
    int n  = j % 25;
    int j2 = j / 25;          // b*256 + t
    int t  = j2 & 255;
    int b  = j2 >> 8;
    int c  = t >> 4;
    int h  = t & 15;
    // src float4 index: (b*819200 + c*51200 + n*2048 + h*128)/4 + w4
    int srcI = b * 204800 + c * 12800 + n * 512 + h * 32 + w4;
    dst[i] = src[srcI];       // dst index == i (coalesced store)
}

// ---------------------------------------------------------------------------
// Row inverse norms over the 3200-dim for Q (y=0) and K (y=1).
// One 256-thread block per row.
// ---------------------------------------------------------------------------
__global__ void norm_kernel() {
    int row = blockIdx.x;                            // b*256 + t, [0, 4096)
    const float4* src = (const float4*)(blockIdx.y == 0 ? g_Qp : g_Kp);
    float sum = 0.f;
    for (int i = threadIdx.x; i < 800; i += 256) {
        float4 vv = src[row * 800 + i];
        sum += vv.x * vv.x + vv.y * vv.y + vv.z * vv.z + vv.w * vv.w;
    }
    __shared__ float red[32];
    #pragma unroll
    for (int o = 16; o > 0; o >>= 1) sum += __shfl_xor_sync(~0u, sum, o);
    if ((threadIdx.x & 31) == 0) red[threadIdx.x >> 5] = sum;
    __syncthreads();
    if (threadIdx.x < 32) {
        float s2 = (threadIdx.x < 8) ? red[threadIdx.x] : 0.f;
        #pragma unroll
        for (int o = 4; o > 0; o >>= 1) s2 += __shfl_xor_sync(~0u, s2, o);
        if (threadIdx.x == 0) {
            float inv = 1.f / fmaxf(sqrtf(s2), 1e-12f);
            (blockIdx.y == 0 ? g_invq : g_invk)[row] = inv;
        }
    }
}

// ---------------------------------------------------------------------------
// tf32 mma.sync helper: D += A(16x8) * B(8x8)
// ---------------------------------------------------------------------------
__device__ __forceinline__ void mma_tf32(float* c, const uint32_t* a, const uint32_t* b) {
    asm volatile(
        "mma.sync.aligned.m16n8k8.row.col.f32.tf32.tf32.f32 "
        "{%0,%1,%2,%3}, {%4,%5,%6,%7}, {%8,%9}, {%0,%1,%2,%3};\n"
        : "+f"(c[0]), "+f"(c[1]), "+f"(c[2]), "+f"(c[3])
        : "r"(a[0]), "r"(a[1]), "r"(a[2]), "r"(a[3]), "r"(b[0]), "r"(b[1]));
}

// ---------------------------------------------------------------------------
// GEMM1: att_raw[b][t][r] = sum_s Qp[b][t][s] * Kp[b][r][s]
// CTA tile 64(t) x 128(r), K-chunk 32, 4 warps (warp tile 32x64).
// Grid: (8, 16)  [bx: tm(0..3) x tn(0..1)]
// ---------------------------------------------------------------------------
#define KC 32
#define AST 36   // As row stride (floats)
#define BST 36   // Bs row stride (floats)

__global__ __launch_bounds__(128) void gemm1_kernel() {
    __shared__ float As[64 * AST];    // [m][k]
    __shared__ float Bs[128 * BST];   // [r][k]

    int b  = blockIdx.y;
    int tm = blockIdx.x >> 1;
    int tn = blockIdx.x & 1;
    int t0 = tm * 64;
    int r0 = tn * 128;

    int tid  = threadIdx.x;
    int warp = tid >> 5, lane = tid & 31;
    int wm = warp >> 1, wn = warp & 1;       // 2x2 warp grid, warp tile 32x64
    int gid = lane >> 2, tig = lane & 3;

    const float* Ag = g_Qp + (size_t)(b * 256 + t0) * SD;
    const float* Bg = g_Kp + (size_t)(b * 256 + r0) * SD;

    float acc[2][8][4];
    #pragma unroll
    for (int mi = 0; mi < 2; mi++)
        #pragma unroll
        for (int ni = 0; ni < 8; ni++)
            #pragma unroll
            for (int x = 0; x < 4; x++) acc[mi][ni][x] = 0.f;

    int rowA = tid >> 3;       // 0..15
    int c4   = tid & 7;        // 0..7 (f4 col)

    for (int ks = 0; ks < SD; ks += KC) {
        // stage global->regs (overlaps previous iter compute)
        float4 la[4], lb[8];
        #pragma unroll
        for (int p = 0; p < 4; p++)
            la[p] = *(const float4*)(Ag + (size_t)(p * 16 + rowA) * SD + ks + c4 * 4);
        #pragma unroll
        for (int p = 0; p < 8; p++)
            lb[p] = *(const float4*)(Bg + (size_t)(p * 16 + rowA) * SD + ks + c4 * 4);

        __syncthreads();   // previous compute done
        #pragma unroll
        for (int p = 0; p < 4; p++)
            *(float4*)(&As[(p * 16 + rowA) * AST + c4 * 4]) = la[p];
        #pragma unroll
        for (int p = 0; p < 8; p++)
            *(float4*)(&Bs[(p * 16 + rowA) * BST + c4 * 4]) = lb[p];
        __syncthreads();

        #pragma unroll
        for (int kk = 0; kk < KC; kk += 8) {
            uint32_t af[2][4];
            #pragma unroll
            for (int mi = 0; mi < 2; mi++) {
                int rA = wm * 32 + mi * 16 + gid;
                af[mi][0] = __float_as_uint(As[rA * AST + kk + tig]);
                af[mi][1] = __float_as_uint(As[(rA + 8) * AST + kk + tig]);
                af[mi][2] = __float_as_uint(As[rA * AST + kk + tig + 4]);
                af[mi][3] = __float_as_uint(As[(rA + 8) * AST + kk + tig + 4]);
            }
            uint32_t bf[8][2];
            #pragma unroll
            for (int ni = 0; ni < 8; ni++) {
                int rB = wn * 64 + ni * 8 + gid;
                bf[ni][0] = __float_as_uint(Bs[rB * BST + kk + tig]);
                bf[ni][1] = __float_as_uint(Bs[rB * BST + kk + tig + 4]);
            }
            #pragma unroll
            for (int mi = 0; mi < 2; mi++)
                #pragma unroll
                for (int ni = 0; ni < 8; ni++)
                    mma_tf32(acc[mi][ni], af[mi], bf[ni]);
        }
    }

    // epilogue: raw att (scaling applied in softmax kernel)
    float* Cg = g_att + (size_t)b * 256 * 256;
    #pragma unroll
    for (int mi = 0; mi < 2; mi++) {
        int row = t0 + wm * 32 + mi * 16 + gid;
        #pragma unroll
        for (int ni = 0; ni < 8; ni++) {
            int col = r0 + wn * 64 + ni * 8 + tig * 2;
            *(float2*)(&Cg[row * 256 + col])       = make_float2(acc[mi][ni][0], acc[mi][ni][1]);
            *(float2*)(&Cg[(row + 8) * 256 + col]) = make_float2(acc[mi][ni][2], acc[mi][ni][3]);
        }
    }
}

// ---------------------------------------------------------------------------
// Softmax: scale by invq[t]*invk[r], causal mask (r<=t), softmax over r.
// One 256-thread block per (b, t) row; in-place on g_att.
// ---------------------------------------------------------------------------
__global__ void softmax_kernel() {
    __shared__ float red[33];
    int bt = blockIdx.x;          // b*256 + t
    int t  = bt & 255;
    int b  = bt >> 8;
    int r  = threadIdx.x;
    float* row = g_att + (size_t)bt * 256;

    float x = row[r] * g_invq[bt] * g_invk[(b << 8) + r];
    if (r > t) x = -1e15f;

    float m = x;
    #pragma unroll
    for (int o = 16; o > 0; o >>= 1) m = fmaxf(m, __shfl_xor_sync(~0u, m, o));
    if ((r & 31) == 0) red[r >> 5] = m;
    __syncthreads();
    if (r < 32) {
        float m2 = (r < 8) ? red[r] : -3.4e38f;
        #pragma unroll
        for (int o = 4; o > 0; o >>= 1) m2 = fmaxf(m2, __shfl_xor_sync(~0u, m2, o));
        if (r == 0) red[32] = m2;
    }
    __syncthreads();
    float e = expf(x - red[32]);

    float s = e;
    #pragma unroll
    for (int o = 16; o > 0; o >>= 1) s += __shfl_xor_sync(~0u, s, o);
    if ((r & 31) == 0) red[r >> 5] = s;
    __syncthreads();
    if (r < 32) {
        float s2 = (r < 8) ? red[r] : 0.f;
        #pragma unroll
        for (int o = 4; o > 0; o >>= 1) s2 += __shfl_xor_sync(~0u, s2, o);
        if (r == 0) red[32] = s2;
    }
    __syncthreads();
    row[r] = e / red[32];
}

// ---------------------------------------------------------------------------
// GEMM2: out[b][t][s] = sum_r att[b][t][r] * Vp[b][r][s]  + Vp[b][t][s]
// CTA tile 64(t) x 128(s), K=256 in chunks of 32. Epilogue writes d_out
// directly: a 128-wide s-tile is one fixed n -> contiguous w run.
// Grid: (100, 16)  [bx = tm*25 + sn]
// ---------------------------------------------------------------------------
#define B2ST 136   // Bs row stride (floats), conflict-free for fragment reads

__global__ __launch_bounds__(128) void gemm2_kernel(float* __restrict__ out) {
    __shared__ float As[64 * AST];     // att [m][k]
    __shared__ float Bs[KC * B2ST];    // V   [k][n], n = 128

    int b  = blockIdx.y;
    int bx = blockIdx.x;
    int tm = bx / 25;
    int sn = bx % 25;
    int t0 = tm * 64;
    int s0 = sn * 128;

    int tid  = threadIdx.x;
    int warp = tid >> 5, lane = tid & 31;
    int wm = warp >> 1, wn = warp & 1;
    int gid = lane >> 2, tig = lane & 3;

    const float* Ag = g_att + (size_t)(b * 256 + t0) * 256;
    const float* Bg = g_Vp + (size_t)b * 256 * SD + s0;

    float acc[2][8][4];
    #pragma unroll
    for (int mi = 0; mi < 2; mi++)
        #pragma unroll
        for (int ni = 0; ni < 8; ni++)
            #pragma unroll
            for (int x = 0; x < 4; x++) acc[mi][ni][x] = 0.f;

    int rowA = tid >> 3;   // 0..15
    int c4a  = tid & 7;
    int rowB = tid >> 5;   // 0..3
    int c4b  = tid & 31;

    for (int ks = 0; ks < 256; ks += KC) {
        float4 la[4], lb[8];
        #pragma unroll
        for (int p = 0; p < 4; p++)
            la[p] = *(const float4*)(Ag + (size_t)(p * 16 + rowA) * 256 + ks + c4a * 4);
        #pragma unroll
        for (int p = 0; p < 8; p++)
            lb[p] = *(const float4*)(Bg + (size_t)(ks + p * 4 + rowB) * SD + c4b * 4);

        __syncthreads();
        #pragma unroll
        for (int p = 0; p < 4; p++)
            *(float4*)(&As[(p * 16 + rowA) * AST + c4a * 4]) = la[p];
        #pragma unroll
        for (int p = 0; p < 8; p++)
            *(float4*)(&Bs[(p * 4 + rowB) * B2ST + c4b * 4]) = lb[p];
        __syncthreads();

        #pragma unroll
        for (int kk = 0; kk < KC; kk += 8) {
            uint32_t af[2][4];
            #pragma unroll
            for (int mi = 0; mi < 2; mi++) {
                int rA = wm * 32 + mi * 16 + gid;
                af[mi][0] = __float_as_uint(As[rA * AST + kk + tig]);
                af[mi][1] = __float_as_uint(As[(rA + 8) * AST + kk + tig]);
                af[mi][2] = __float_as_uint(As[rA * AST + kk + tig + 4]);
                af[mi][3] = __float_as_uint(As[(rA + 8) * AST + kk + tig + 4]);
            }
            uint32_t bf[8][2];
            #pragma unroll
            for (int ni = 0; ni < 8; ni++) {
                int cB = wn * 64 + ni * 8 + gid;
                bf[ni][0] = __float_as_uint(Bs[(kk + tig) * B2ST + cB]);
                bf[ni][1] = __float_as_uint(Bs[(kk + tig + 4) * B2ST + cB]);
            }
            #pragma unroll
            for (int mi = 0; mi < 2; mi++)
                #pragma unroll
                for (int ni = 0; ni < 8; ni++)
                    mma_tf32(acc[mi][ni], af[mi], bf[ni]);
        }
    }

    // epilogue: add V buffer, write output in original (b,c,n,h,w) layout
    #pragma unroll
    for (int mi = 0; mi < 2; mi++) {
        #pragma unroll
        for (int half = 0; half < 2; half++) {
            int t = t0 + wm * 32 + mi * 16 + gid + half * 8;
            size_t obase = (size_t)b * ELEM_PER_B + (size_t)(t >> 4) * 51200
                         + (size_t)sn * 2048 + (size_t)(t & 15) * 128;
            const float* vrow = g_Vp + (size_t)(b * 256 + t) * SD + s0;
            #pragma unroll
            for (int ni = 0; ni < 8; ni++) {
                int w = wn * 64 + ni * 8 + tig * 2;
                float2 vv = *(const float2*)(vrow + w);
                float2 o;
                o.x = acc[mi][ni][half * 2 + 0] + vv.x;
                o.y = acc[mi][ni][half * 2 + 1] + vv.y;
                *(float2*)(out + obase + w) = o;
            }
        }
    }
}

// ---------------------------------------------------------------------------
// Launch
// ---------------------------------------------------------------------------
extern "C" void kernel_launch(void* const* d_in, const int* in_sizes, int n_in,
                              void* d_out, int out_size) {
    const float4* q = (const float4*)d_in[0];
    const float4* k = (const float4*)d_in[1];
    const float4* v = (const float4*)d_in[2];
    float* out = (float*)d_out;

    pack_kernel<<<dim3(12800, 3), 256>>>(q, k, v);
    norm_kernel<<<dim3(4096, 2), 256>>>();
    gemm1_kernel<<<dim3(8, NB), 128>>>();
    softmax_kernel<<<4096, 256>>>();
    gemm2_kernel<<<dim3(100, NB), 128>>>(out);
}

// round 7
// speedup vs baseline: 1.6844x; 1.6844x over previous
#include <cuda_runtime.h>
#include <cstdint>

// Problem constants
#define NB 16      // batches
#define CH 256     // c*h rows
#define SD 3200    // contraction dim, ordered s' = n*128 + w
#define ELEM_PER_B 819200   // 16*25*16*128 floats per batch per tensor
#define NSPLIT 2   // split-K factor for GEMM1
#define KHALF 1600 // SD / NSPLIT

// Scratch (static device globals only)
__device__ float g_att[NSPLIT][NB * CH * CH];  // partials; [0] holds softmax result
__device__ float g_invq[NB * CH];
__device__ float g_invk[NB * CH];

// ---------------------------------------------------------------------------
// Row inverse norms over the 3200-dim for Q (y=0) and K (y=1), reading the
// ORIGINAL (b,c,n,h,w) layout. Coalesced in 128B runs.
// ---------------------------------------------------------------------------
__global__ void norm_kernel(const float4* __restrict__ q,
                            const float4* __restrict__ k) {
    int row = blockIdx.x;                  // b*256 + t
    int t = row & 255, b = row >> 8;
    const float4* src = (blockIdx.y == 0 ? q : k)
        + (size_t)b * 204800 + (size_t)(t >> 4) * 12800 + (size_t)(t & 15) * 32;
    float sum = 0.f;
    for (int i = threadIdx.x; i < 800; i += 256) {
        int n = i >> 5, w4 = i & 31;
        float4 vv = src[n * 512 + w4];
        sum += vv.x * vv.x + vv.y * vv.y + vv.z * vv.z + vv.w * vv.w;
    }
    __shared__ float red[32];
    #pragma unroll
    for (int o = 16; o > 0; o >>= 1) sum += __shfl_xor_sync(~0u, sum, o);
    if ((threadIdx.x & 31) == 0) red[threadIdx.x >> 5] = sum;
    __syncthreads();
    if (threadIdx.x < 32) {
        float s2 = (threadIdx.x < 8) ? red[threadIdx.x] : 0.f;
        #pragma unroll
        for (int o = 4; o > 0; o >>= 1) s2 += __shfl_xor_sync(~0u, s2, o);
        if (threadIdx.x == 0) {
            float inv = 1.f / fmaxf(sqrtf(s2), 1e-12f);
            (blockIdx.y == 0 ? g_invq : g_invk)[row] = inv;
        }
    }
}

// ---------------------------------------------------------------------------
// tf32 mma.sync helper: D += A(16x8) * B(8x8)
// ---------------------------------------------------------------------------
__device__ __forceinline__ void mma_tf32(float* c, const uint32_t* a, const uint32_t* b) {
    asm volatile(
        "mma.sync.aligned.m16n8k8.row.col.f32.tf32.tf32.f32 "
        "{%0,%1,%2,%3}, {%4,%5,%6,%7}, {%8,%9}, {%0,%1,%2,%3};\n"
        : "+f"(c[0]), "+f"(c[1]), "+f"(c[2]), "+f"(c[3])
        : "r"(a[0]), "r"(a[1]), "r"(a[2]), "r"(a[3]), "r"(b[0]), "r"(b[1]));
}

// ---------------------------------------------------------------------------
// GEMM1 (split-K x2, pipelined): att_part[half] = partial Q.K^T
// CTA tile 64x128, K-chunk 32, 4 warps. Grid: (16, 16); bx = half*8+tm*2+tn.
// Loop rotated: smem-store -> sync -> issue NEXT global loads -> compute ->
// sync, so global latency hides under MMA compute.
// ---------------------------------------------------------------------------
#define KC 32
#define AST 36
#define BST 36

__global__ __launch_bounds__(128) void gemm1_kernel(const float* __restrict__ q,
                                                    const float* __restrict__ k) {
    __shared__ float As[64 * AST];    // [m][k]
    __shared__ float Bs[128 * BST];   // [r][k]

    int b    = blockIdx.y;
    int half = blockIdx.x >> 3;
    int tm   = (blockIdx.x >> 1) & 3;
    int tn   = blockIdx.x & 1;
    int t0 = tm * 64;
    int r0 = tn * 128;

    int tid  = threadIdx.x;
    int warp = tid >> 5, lane = tid & 31;
    int wm = warp >> 1, wn = warp & 1;
    int gid = lane >> 2, tig = lane & 3;

    const float* Ab = q + (size_t)b * ELEM_PER_B;
    const float* Bb = k + (size_t)b * ELEM_PER_B;

    float acc[2][8][4];
    #pragma unroll
    for (int mi = 0; mi < 2; mi++)
        #pragma unroll
        for (int ni = 0; ni < 8; ni++)
            #pragma unroll
            for (int x = 0; x < 4; x++) acc[mi][ni][x] = 0.f;

    int rowA = tid >> 3;       // 0..15 = (t&15) of the loaded row
    int c4   = tid & 7;        // 16B column within 128B chunk

    const int ks0 = half * KHALF;
    const int ksend = ks0 + KHALF;

    float4 la[4], lb[8];
    // prologue loads (chunk ks0)
    {
        int soff = (ks0 >> 7) * 2048 + (ks0 & 127) + c4 * 4;
        #pragma unroll
        for (int p = 0; p < 4; p++)
            la[p] = *(const float4*)(Ab + (size_t)(t0 / 16 + p) * 51200
                                        + rowA * 128 + soff);
        #pragma unroll
        for (int p = 0; p < 8; p++)
            lb[p] = *(const float4*)(Bb + (size_t)(r0 / 16 + p) * 51200
                                        + rowA * 128 + soff);
    }

    for (int ks = ks0; ks < ksend; ks += KC) {
        __syncthreads();   // smem free (prev compute done)
        #pragma unroll
        for (int p = 0; p < 4; p++)
            *(float4*)(&As[(p * 16 + rowA) * AST + c4 * 4]) = la[p];
        #pragma unroll
        for (int p = 0; p < 8; p++)
            *(float4*)(&Bs[(p * 16 + rowA) * BST + c4 * 4]) = lb[p];
        __syncthreads();

        // issue next chunk's loads; latency hides under compute below
        if (ks + KC < ksend) {
            int ksn = ks + KC;
            int soff = (ksn >> 7) * 2048 + (ksn & 127) + c4 * 4;
            #pragma unroll
            for (int p = 0; p < 4; p++)
                la[p] = *(const float4*)(Ab + (size_t)(t0 / 16 + p) * 51200
                                            + rowA * 128 + soff);
            #pragma unroll
            for (int p = 0; p < 8; p++)
                lb[p] = *(const float4*)(Bb + (size_t)(r0 / 16 + p) * 51200
                                            + rowA * 128 + soff);
        }

        #pragma unroll
        for (int kk = 0; kk < KC; kk += 8) {
            uint32_t af[2][4];
            #pragma unroll
            for (int mi = 0; mi < 2; mi++) {
                int rA = wm * 32 + mi * 16 + gid;
                af[mi][0] = __float_as_uint(As[rA * AST + kk + tig]);
                af[mi][1] = __float_as_uint(As[(rA + 8) * AST + kk + tig]);
                af[mi][2] = __float_as_uint(As[rA * AST + kk + tig + 4]);
                af[mi][3] = __float_as_uint(As[(rA + 8) * AST + kk + tig + 4]);
            }
            uint32_t bf[8][2];
            #pragma unroll
            for (int ni = 0; ni < 8; ni++) {
                int rB = wn * 64 + ni * 8 + gid;
                bf[ni][0] = __float_as_uint(Bs[rB * BST + kk + tig]);
                bf[ni][1] = __float_as_uint(Bs[rB * BST + kk + tig + 4]);
            }
            #pragma unroll
            for (int mi = 0; mi < 2; mi++)
                #pragma unroll
                for (int ni = 0; ni < 8; ni++)
                    mma_tf32(acc[mi][ni], af[mi], bf[ni]);
        }
    }

    float* Cg = g_att[half] + (size_t)b * 256 * 256;
    #pragma unroll
    for (int mi = 0; mi < 2; mi++) {
        int row = t0 + wm * 32 + mi * 16 + gid;
        #pragma unroll
        for (int ni = 0; ni < 8; ni++) {
            int col = r0 + wn * 64 + ni * 8 + tig * 2;
            *(float2*)(&Cg[row * 256 + col])       = make_float2(acc[mi][ni][0], acc[mi][ni][1]);
            *(float2*)(&Cg[(row + 8) * 256 + col]) = make_float2(acc[mi][ni][2], acc[mi][ni][3]);
        }
    }
}

// ---------------------------------------------------------------------------
// Softmax: combine split-K partials, scale by invq[t]*invk[r], causal mask,
// softmax over r. Writes final probs to g_att[0].
// ---------------------------------------------------------------------------
__global__ void softmax_kernel() {
    __shared__ float red[33];
    int bt = blockIdx.x;
    int t  = bt & 255;
    int b  = bt >> 8;
    int r  = threadIdx.x;
    size_t idx = (size_t)bt * 256 + r;

    float x = (g_att[0][idx] + g_att[1][idx]) * g_invq[bt] * g_invk[(b << 8) + r];
    if (r > t) x = -1e15f;

    float m = x;
    #pragma unroll
    for (int o = 16; o > 0; o >>= 1) m = fmaxf(m, __shfl_xor_sync(~0u, m, o));
    if ((r & 31) == 0) red[r >> 5] = m;
    __syncthreads();
    if (r < 32) {
        float m2 = (r < 8) ? red[r] : -3.4e38f;
        #pragma unroll
        for (int o = 4; o > 0; o >>= 1) m2 = fmaxf(m2, __shfl_xor_sync(~0u, m2, o));
        if (r == 0) red[32] = m2;
    }
    __syncthreads();
    float e = expf(x - red[32]);

    float s = e;
    #pragma unroll
    for (int o = 16; o > 0; o >>= 1) s += __shfl_xor_sync(~0u, s, o);
    if ((r & 31) == 0) red[r >> 5] = s;
    __syncthreads();
    if (r < 32) {
        float s2 = (r < 8) ? red[r] : 0.f;
        #pragma unroll
        for (int o = 4; o > 0; o >>= 1) s2 += __shfl_xor_sync(~0u, s2, o);
        if (r == 0) red[32] = s2;
    }
    __syncthreads();
    g_att[0][idx] = e / red[32];
}

// ---------------------------------------------------------------------------
// GEMM2 (pipelined): out[b][t][s] = sum_r att[t][r] * v'[r][s] + v'[t][s]
// CTA tile 64(t) x 128(s), K=256 in chunks of 32. Grid: (100, 16).
// ---------------------------------------------------------------------------
#define B2ST 136

__global__ __launch_bounds__(128) void gemm2_kernel(const float* __restrict__ v,
                                                    float* __restrict__ out) {
    __shared__ float As[64 * AST];     // att [m][k]
    __shared__ float Bs[KC * B2ST];    // V   [k][n], n = 128

    int b  = blockIdx.y;
    int bx = blockIdx.x;
    int tm = bx / 25;
    int sn = bx % 25;
    int t0 = tm * 64;

    int tid  = threadIdx.x;
    int warp = tid >> 5, lane = tid & 31;
    int wm = warp >> 1, wn = warp & 1;
    int gid = lane >> 2, tig = lane & 3;

    const float* Ag = g_att[0] + (size_t)(b * 256 + t0) * 256;
    const float* Vb = v + (size_t)b * ELEM_PER_B + (size_t)sn * 2048;

    float acc[2][8][4];
    #pragma unroll
    for (int mi = 0; mi < 2; mi++)
        #pragma unroll
        for (int ni = 0; ni < 8; ni++)
            #pragma unroll
            for (int x = 0; x < 4; x++) acc[mi][ni][x] = 0.f;

    int rowA = tid >> 3;   // 0..15
    int c4a  = tid & 7;
    int rowB = tid >> 5;   // 0..3
    int c4b  = tid & 31;

    float4 la[4], lb[8];
    // prologue loads (ks = 0)
    {
        #pragma unroll
        for (int p = 0; p < 4; p++)
            la[p] = *(const float4*)(Ag + (size_t)(p * 16 + rowA) * 256 + c4a * 4);
        #pragma unroll
        for (int p = 0; p < 8; p++) {
            int r = p * 4 + rowB;
            lb[p] = *(const float4*)(Vb + (size_t)(r >> 4) * 51200
                                        + (r & 15) * 128 + c4b * 4);
        }
    }

    for (int ks = 0; ks < 256; ks += KC) {
        __syncthreads();
        #pragma unroll
        for (int p = 0; p < 4; p++)
            *(float4*)(&As[(p * 16 + rowA) * AST + c4a * 4]) = la[p];
        #pragma unroll
        for (int p = 0; p < 8; p++)
            *(float4*)(&Bs[(p * 4 + rowB) * B2ST + c4b * 4]) = lb[p];
        __syncthreads();

        if (ks + KC < 256) {
            int ksn = ks + KC;
            #pragma unroll
            for (int p = 0; p < 4; p++)
                la[p] = *(const float4*)(Ag + (size_t)(p * 16 + rowA) * 256
                                            + ksn + c4a * 4);
            #pragma unroll
            for (int p = 0; p < 8; p++) {
                int r = ksn + p * 4 + rowB;
                lb[p] = *(const float4*)(Vb + (size_t)(r >> 4) * 51200
                                            + (r & 15) * 128 + c4b * 4);
            }
        }

        #pragma unroll
        for (int kk = 0; kk < KC; kk += 8) {
            uint32_t af[2][4];
            #pragma unroll
            for (int mi = 0; mi < 2; mi++) {
                int rA = wm * 32 + mi * 16 + gid;
                af[mi][0] = __float_as_uint(As[rA * AST + kk + tig]);
                af[mi][1] = __float_as_uint(As[(rA + 8) * AST + kk + tig]);
                af[mi][2] = __float_as_uint(As[rA * AST + kk + tig + 4]);
                af[mi][3] = __float_as_uint(As[(rA + 8) * AST + kk + tig + 4]);
            }
            uint32_t bf[8][2];
            #pragma unroll
            for (int ni = 0; ni < 8; ni++) {
                int cB = wn * 64 + ni * 8 + gid;
                bf[ni][0] = __float_as_uint(Bs[(kk + tig) * B2ST + cB]);
                bf[ni][1] = __float_as_uint(Bs[(kk + tig + 4) * B2ST + cB]);
            }
            #pragma unroll
            for (int mi = 0; mi < 2; mi++)
                #pragma unroll
                for (int ni = 0; ni < 8; ni++)
                    mma_tf32(acc[mi][ni], af[mi], bf[ni]);
        }
    }

    // epilogue: add V buffer (read at the OUTPUT address in v) and store
    #pragma unroll
    for (int mi = 0; mi < 2; mi++) {
        #pragma unroll
        for (int half = 0; half < 2; half++) {
            int t = t0 + wm * 32 + mi * 16 + gid + half * 8;
            size_t obase = (size_t)b * ELEM_PER_B + (size_t)(t >> 4) * 51200
                         + (size_t)sn * 2048 + (size_t)(t & 15) * 128;
            #pragma unroll
            for (int ni = 0; ni < 8; ni++) {
                int w = wn * 64 + ni * 8 + tig * 2;
                float2 vv = *(const float2*)(v + obase + w);
                float2 o;
                o.x = acc[mi][ni][half * 2 + 0] + vv.x;
                o.y = acc[mi][ni][half * 2 + 1] + vv.y;
                *(float2*)(out + obase + w) = o;
            }
        }
    }
}

// ---------------------------------------------------------------------------
// Launch
// ---------------------------------------------------------------------------
extern "C" void kernel_launch(void* const* d_in, const int* in_sizes, int n_in,
                              void* d_out, int out_size) {
    const float* q = (const float*)d_in[0];
    const float* k = (const float*)d_in[1];
    const float* v = (const float*)d_in[2];
    float* out = (float*)d_out;

    norm_kernel<<<dim3(4096, 2), 256>>>((const float4*)q, (const float4*)k);
    gemm1_kernel<<<dim3(16, NB), 128>>>(q, k);
    softmax_kernel<<<4096, 256>>>();
    gemm2_kernel<<<dim3(100, NB), 128>>>(v, out);
}